// round 10
// baseline (speedup 1.0000x reference)
#include <cuda_runtime.h>
#include <cstdint>

#define BT20   2621440u     // B*20 (elements per head slab)
#define HALFN  52428800u    // 20*BT20
#define TPB    64

// ---- packed f32x2 helpers ----
__device__ __forceinline__ unsigned long long pack2(float lo, float hi) {
    unsigned long long r;
    asm("mov.b64 %0, {%1, %2};" : "=l"(r) : "f"(lo), "f"(hi));
    return r;
}
__device__ __forceinline__ void unpack2(unsigned long long v, float &lo, float &hi) {
    asm("mov.b64 {%0, %1}, %2;" : "=f"(lo), "=f"(hi) : "l"(v));
}
__device__ __forceinline__ void fma2(unsigned long long &d, unsigned long long a,
                                     unsigned long long b) {
    asm("fma.rn.f32x2 %0, %1, %2, %0;" : "+l"(d) : "l"(a), "l"(b));
}
__device__ __forceinline__ void add2(unsigned long long &d, unsigned long long a) {
    asm("add.rn.f32x2 %0, %0, %1;" : "+l"(d) : "l"(a));
}
__device__ __forceinline__ unsigned long long f2lo(const float4 &v) { return pack2(v.x, v.y); }
__device__ __forceinline__ unsigned long long f2hi(const float4 &v) { return pack2(v.z, v.w); }

// integer add on the FMA pipe (IMAD); 'one' is runtime-opaque
__device__ __forceinline__ uint32_t addm(uint32_t a, uint32_t b, uint32_t one) {
    uint32_t r;
    asm("mad.lo.u32 %0, %1, %2, %3;" : "=r"(r) : "r"(b), "r"(one), "r"(a));
    return r;
}

// ---- Threefry-2x32-20, key (0,42); returns ~(o0^o1); keep-bit in MSB ----
// (verified bit-exact vs JAX partitionable threefry, rounds 2-9)
__device__ __forceinline__ uint32_t tf_mix(uint32_t x1_init, uint32_t one) {
    const uint32_t ks1 = 42u;
    const uint32_t ks2 = 0x1BD11BDAu ^ 42u;
    uint32_t x1 = x1_init;          // c1 + ks1
    uint32_t x0 = x1;               // round 1 add with x0=0
    x1 = __funnelshift_l(x1, x1, 13) ^ x0;
#define TF_R(r)  { x0 = addm(x0, x1, one); \
                   x1 = __funnelshift_l(x1, x1, (r)); x1 ^= x0; }
    TF_R(15) TF_R(26) TF_R(6)
    x0 += ks1;  x1 += ks2 + 1u;
    TF_R(17) TF_R(29) TF_R(16) TF_R(24)
    x0 += ks2;  x1 += 2u;
    TF_R(13) TF_R(15) TF_R(26) TF_R(6)
    x1 += ks1 + 3u;
    TF_R(17) TF_R(29) TF_R(16) TF_R(24)
    x0 += ks1;  x1 += ks2 + 4u;
    TF_R(13) TF_R(15) TF_R(26) TF_R(6)
    x0 += ks2;  x1 += 5u;
#undef TF_R
    return ~(x0 ^ x1);
}

// keep-multiplier 2.0f / 0.0f from mask bit o
__device__ __forceinline__ float keepf(uint32_t m, int o) {
    return __uint_as_float((uint32_t)((int)(m << (31 - o)) >> 31) & 0x40000000u);
}

// trunk half for one row: 32 dims (incl pad zeros) -> 16 packed f32x2
__device__ __forceinline__ void trunk_half(const float* __restrict__ x, unsigned row,
                                           const float* sW1p, const float* sb1p,
                                           unsigned cbase, unsigned long long* h2h) {
    unsigned long long x2[10];
    const float4* xp = (const float4*)(x + (size_t)row * 20);
    #pragma unroll
    for (int i = 0; i < 5; i++) {
        float4 v = xp[i];
        x2[2*i]   = f2lo(v);
        x2[2*i+1] = f2hi(v);
    }
    #pragma unroll
    for (int i = 0; i < 16; i++) {
        unsigned long long a0 = 0ull, a1 = 0ull, a2 = 0ull, a3 = 0ull;
        const float4* w0 = (const float4*)(sW1p + (cbase + 2*i) * 20);
        const float4* w1 = w0 + 5;
        #pragma unroll
        for (int d = 0; d < 5; d++) {
            float4 v0 = w0[d], v1 = w1[d];
            fma2(a0, x2[2*d],   f2lo(v0));
            fma2(a2, x2[2*d+1], f2hi(v0));
            fma2(a1, x2[2*d],   f2lo(v1));
            fma2(a3, x2[2*d+1], f2hi(v1));
        }
        add2(a0, a2);
        add2(a1, a3);
        float s0a, s0b, s1a, s1b;
        unpack2(a0, s0a, s0b);
        unpack2(a1, s1a, s1b);
        h2h[i] = pack2(fmaxf(s0a + s0b + sb1p[cbase + 2*i],   0.f),
                       fmaxf(s1a + s1b + sb1p[cbase + 2*i+1], 0.f));
    }
}

// ===== fused kernel: split-d (lane ^ 16) x 2 rows per lane-pair =============
__global__ __launch_bounds__(TPB, 8)
void fused_kernel(const float* __restrict__ x,
                  const float* __restrict__ W1,
                  const float* __restrict__ b1,
                  const float* __restrict__ Wh,
                  const float* __restrict__ bh,
                  float* __restrict__ out,
                  uint32_t one)
{
    __shared__ __align__(16) float sW1p[64 * 20];  // rows 60..63 zero
    __shared__           float sb1p[64];           // 60..63 zero
    __shared__ __align__(16) float sbh[800];       // [40][20]
    __shared__ __align__(16) float sWhA[20 * 64];  // Wh[k],    rows padded to 64
    __shared__ __align__(16) float sWhB[20 * 64];  // Wh[k+20], rows padded to 64

    const int tid = threadIdx.x;

    for (int i = tid; i < 300; i += TPB)
        ((float4*)sW1p)[i] = ((const float4*)W1)[i];
    for (int i = tid; i < 200; i += TPB)
        ((float4*)sbh)[i] = ((const float4*)bh)[i];
    if (tid < 20)                                   // sW1p rows 60..63 = 0
        ((float4*)sW1p)[300 + tid] = make_float4(0.f, 0.f, 0.f, 0.f);
    if (tid < 64) sb1p[tid] = (tid < 60) ? b1[tid] : 0.f;
    __syncthreads();

    const unsigned lane = (unsigned)tid & 31u;
    const unsigned warp = (unsigned)tid >> 5;
    const unsigned half = lane >> 4;                // 0: d 0..31, 1: d 32..63
    const unsigned r    = lane & 15u;
    const unsigned rowA = blockIdx.x * 64u + warp * 32u + r;   // row a
    const unsigned rowB = rowA + 16u;                          // row b
    const unsigned cbase = half * 32u;

    // ---- trunk halves for both rows (sequential to cap reg pressure) ----
    unsigned long long h2a[16], h2b[16];
    trunk_half(x, rowA, sW1p, sb1p, cbase, h2a);
    trunk_half(x, rowB, sW1p, sb1p, cbase, h2b);

    const unsigned baseA = rowA * 20u;
    const unsigned baseB = rowB * 20u;
    const unsigned hoff  = half * HALFN;            // head offset in element space

    // ---- prologue masks (k = 0), this lane's head = 20*half ----
    uint32_t mA = 0u, mB = 0u;
    {
        const uint32_t ja = hoff + baseA + 42u;
        const uint32_t jb = hoff + baseB + 42u;
        #pragma unroll
        for (int o = 0; o < 20; o++) {
            mA |= (tf_mix(ja + (unsigned)o, one) >> 31) << o;
            mB |= (tf_mix(jb + (unsigned)o, one) >> 31) << o;
        }
    }

    for (int k = 0; k < 20; k++) {
        __syncthreads();   // protect previous iteration's sWh reads
        const float4* srcA = (const float4*)(Wh + (size_t)k        * 1200);
        const float4* srcB = (const float4*)(Wh + (size_t)(k + 20) * 1200);
        #pragma unroll
        for (int i = tid; i < 320; i += TPB) {      // padded 16-float4 rows
            int o_  = i >> 4, j_ = i & 15;
            float4 v0 = (j_ < 15) ? srcA[o_ * 15 + j_] : make_float4(0.f,0.f,0.f,0.f);
            float4 v1 = (j_ < 15) ? srcB[o_ * 15 + j_] : make_float4(0.f,0.f,0.f,0.f);
            ((float4*)sWhA)[i] = v0;
            ((float4*)sWhB)[i] = v1;
        }
        __syncthreads();

        uint32_t nA = 0u, nB = 0u;
        const uint32_t nbaseA = (unsigned)(k + 1) * BT20 + hoff + baseA + 42u;
        const uint32_t nbaseB = (unsigned)(k + 1) * BT20 + hoff + baseB + 42u;
        const float* biasRow = sbh + (k + 20 * (int)half) * 20;

        #pragma unroll 1
        for (int oc = 0; oc < 5; oc++) {
            float yva[4], yvb[4];
            #pragma unroll
            for (int u = 0; u < 4; u++) {
                const int o = oc * 4 + u;
                const float4* wA = (const float4*)(sWhA + o * 64 + cbase);
                const float4* wB = (const float4*)(sWhB + o * 64 + cbase);
                // 8 chains: {head A,B} x {row a,b}; one weight feeds 4 fma2
                unsigned long long aa = 0ull, ab = 0ull;   // head A rows a,b
                unsigned long long ba = 0ull, bb = 0ull;   // head B rows a,b
                #pragma unroll
                for (int d = 0; d < 8; d++) {
                    float4 va = wA[d];
                    float4 vb = wB[d];
                    unsigned long long alo = f2lo(va), ahi = f2hi(va);
                    unsigned long long blo = f2lo(vb), bhi = f2hi(vb);
                    fma2(aa, alo, h2a[2*d]);
                    fma2(aa, ahi, h2a[2*d+1]);
                    fma2(ab, alo, h2b[2*d]);
                    fma2(ab, ahi, h2b[2*d+1]);
                    fma2(ba, blo, h2a[2*d]);
                    fma2(ba, bhi, h2a[2*d+1]);
                    fma2(bb, blo, h2b[2*d]);
                    fma2(bb, bhi, h2b[2*d+1]);
                }
                float p, q;
                unpack2(aa, p, q); float hAa = p + q;   // half-dots
                unpack2(ab, p, q); float hAb = p + q;
                unpack2(ba, p, q); float hBa = p + q;
                unpack2(bb, p, q); float hBb = p + q;

                // exchange: send the head we don't own, keep the one we do
                float sa = half ? hAa : hBa;            // row a outgoing
                float sb_ = half ? hAb : hBb;           // row b outgoing
                float ra = __shfl_xor_sync(0xffffffffu, sa, 16);
                float rb = __shfl_xor_sync(0xffffffffu, sb_, 16);
                float ta = (half ? hBa : hAa) + ra;     // this lane's head, row a
                float tb = (half ? hBb : hAb) + rb;     // row b

                const float bias = biasRow[o];
                yva[u] = fmaxf(ta + bias, 0.f) * keepf(mA, o);
                yvb[u] = fmaxf(tb + bias, 0.f) * keepf(mB, o);

                // 2 threefry blocks toward next-k masks (fills stall slots)
                nA |= (tf_mix(nbaseA + (unsigned)o, one) >> 31) << o;
                nB |= (tf_mix(nbaseB + (unsigned)o, one) >> 31) << o;
            }
            const size_t koff = (size_t)k * BT20 + (size_t)hoff;
            *(float4*)(out + koff + baseA + oc * 4) =
                make_float4(yva[0], yva[1], yva[2], yva[3]);
            *(float4*)(out + koff + baseB + oc * 4) =
                make_float4(yvb[0], yvb[1], yvb[2], yvb[3]);
        }
        mA = nA;
        mB = nB;
    }
}

extern "C" void kernel_launch(void* const* d_in, const int* in_sizes, int n_in,
                              void* d_out, int out_size) {
    const float* x  = (const float*)d_in[0];   // [131072, 20]
    const float* W1 = (const float*)d_in[1];   // [60, 20]
    const float* b1 = (const float*)d_in[2];   // [60]
    const float* Wh = (const float*)d_in[3];   // [40, 20, 60]
    const float* bh = (const float*)d_in[4];   // [40, 20]
    float* out = (float*)d_out;                // [40, 131072, 1, 20]

    const int rows = in_sizes[0] / 20;         // 131072
    fused_kernel<<<rows / 64, TPB>>>(x, W1, b1, Wh, bh, out, 1u);
}

// round 11
// speedup vs baseline: 1.0683x; 1.0683x over previous
#include <cuda_runtime.h>
#include <cstdint>

#define BT20   2621440u     // B*20 (elements per head slab)
#define HALFN  52428800u    // 20*BT20
#define TPB    64

// ---- packed f32x2 helpers ----
__device__ __forceinline__ unsigned long long pack2(float lo, float hi) {
    unsigned long long r;
    asm("mov.b64 %0, {%1, %2};" : "=l"(r) : "f"(lo), "f"(hi));
    return r;
}
__device__ __forceinline__ void unpack2(unsigned long long v, float &lo, float &hi) {
    asm("mov.b64 {%0, %1}, %2;" : "=f"(lo), "=f"(hi) : "l"(v));
}
__device__ __forceinline__ void fma2(unsigned long long &d, unsigned long long a,
                                     unsigned long long b) {
    asm("fma.rn.f32x2 %0, %1, %2, %0;" : "+l"(d) : "l"(a), "l"(b));
}
__device__ __forceinline__ void add2(unsigned long long &d, unsigned long long a) {
    asm("add.rn.f32x2 %0, %0, %1;" : "+l"(d) : "l"(a));
}
__device__ __forceinline__ unsigned long long f2lo(const float4 &v) { return pack2(v.x, v.y); }
__device__ __forceinline__ unsigned long long f2hi(const float4 &v) { return pack2(v.z, v.w); }

// integer add on the FMA pipe (IMAD); 'one' is runtime-opaque
__device__ __forceinline__ uint32_t addm(uint32_t a, uint32_t b, uint32_t one) {
    uint32_t r;
    asm("mad.lo.u32 %0, %1, %2, %3;" : "=r"(r) : "r"(b), "r"(one), "r"(a));
    return r;
}
// bit insert on the FMA pipe: w += bit << o  (bit in {0,1}, (1<<o) literal)
__device__ __forceinline__ void insb(uint32_t &w, uint32_t bit, uint32_t sh1) {
    asm("mad.lo.u32 %0, %1, %2, %0;" : "+r"(w) : "r"(bit), "r"(sh1));
}

// ---- Threefry-2x32-20, key (0,42); returns ~(o0^o1); keep-bit in MSB ----
// (verified bit-exact vs JAX partitionable threefry, rounds 2-10)
__device__ __forceinline__ uint32_t tf_mix(uint32_t x1_init, uint32_t one) {
    const uint32_t ks1 = 42u;
    const uint32_t ks2 = 0x1BD11BDAu ^ 42u;
    uint32_t x1 = x1_init;          // c1 + ks1
    uint32_t x0 = x1;               // round 1 add with x0=0
    x1 = __funnelshift_l(x1, x1, 13) ^ x0;
#define TF_R(r)  { x0 = addm(x0, x1, one); \
                   x1 = __funnelshift_l(x1, x1, (r)); x1 ^= x0; }
    TF_R(15) TF_R(26) TF_R(6)
    x0 += ks1;  x1 += ks2 + 1u;
    TF_R(17) TF_R(29) TF_R(16) TF_R(24)
    x0 += ks2;  x1 += 2u;
    TF_R(13) TF_R(15) TF_R(26) TF_R(6)
    x1 += ks1 + 3u;
    TF_R(17) TF_R(29) TF_R(16) TF_R(24)
    x0 += ks1;  x1 += ks2 + 4u;
    TF_R(13) TF_R(15) TF_R(26) TF_R(6)
    x0 += ks2;  x1 += 5u;
#undef TF_R
    return ~(x0 ^ x1);
}

// keep-multiplier 2.0f / 0.0f from mask bit o
__device__ __forceinline__ float keepf(uint32_t m, int o) {
    return __uint_as_float((uint32_t)((int)(m << (31 - o)) >> 31) & 0x40000000u);
}

// ================= fused kernel: trunk + heads + inline dropout =============
__global__ __launch_bounds__(TPB, 10)
void fused_kernel(const float* __restrict__ x,
                  const float* __restrict__ W1,
                  const float* __restrict__ b1,
                  const float* __restrict__ Wh,
                  const float* __restrict__ bh,
                  float* __restrict__ out,
                  uint32_t one)
{
    __shared__ __align__(16) float sW1[1200];   // [60][20]
    __shared__           float sb1[64];
    __shared__ __align__(16) float sbh[800];    // [40][20]
    __shared__ __align__(16) float sWhA[1200];  // Wh[k]      [20][60]
    __shared__ __align__(16) float sWhB[1200];  // Wh[k+20]   [20][60]

    const int tid = threadIdx.x;

    for (int i = tid; i < 300; i += TPB)
        ((float4*)sW1)[i] = ((const float4*)W1)[i];
    for (int i = tid; i < 200; i += TPB)
        ((float4*)sbh)[i] = ((const float4*)bh)[i];
    if (tid < 60) sb1[tid] = b1[tid];
    __syncthreads();

    const unsigned b = blockIdx.x * TPB + (unsigned)tid;   // one row per thread
    const unsigned base_b = b * 20u;

    // ---- trunk: h = relu(W1 @ x + b1), packed as 30 f32x2 regs ----
    unsigned long long h2[30];
    {
        unsigned long long x2[10];
        const float4* xp = (const float4*)(x + (size_t)b * 20);
        #pragma unroll
        for (int i = 0; i < 5; i++) {
            float4 v = xp[i];
            x2[2*i]   = f2lo(v);
            x2[2*i+1] = f2hi(v);
        }
        #pragma unroll
        for (int i = 0; i < 30; i++) {
            unsigned long long a0 = 0ull, a1 = 0ull, a2 = 0ull, a3 = 0ull;
            const float4* w0 = (const float4*)(sW1 + (2*i)   * 20);
            const float4* w1 = (const float4*)(sW1 + (2*i+1) * 20);
            #pragma unroll
            for (int d = 0; d < 5; d++) {
                float4 v0 = w0[d], v1 = w1[d];
                fma2(a0, x2[2*d],   f2lo(v0));
                fma2(a2, x2[2*d+1], f2hi(v0));
                fma2(a1, x2[2*d],   f2lo(v1));
                fma2(a3, x2[2*d+1], f2hi(v1));
            }
            add2(a0, a2);
            add2(a1, a3);
            float s0a, s0b, s1a, s1b;
            unpack2(a0, s0a, s0b);
            unpack2(a1, s1a, s1b);
            h2[i] = pack2(fmaxf(s0a + s0b + sb1[2*i],   0.f),
                          fmaxf(s1a + s1b + sb1[2*i+1], 0.f));
        }
    }

    // ---- prologue: mask words for k = 0 pair ----
    uint32_t mA = 0u, mB = 0u;
    #pragma unroll
    for (int o = 0; o < 20; o++) {
        uint32_t jA = base_b + (unsigned)o + 42u;       // j + ks1
        insb(mA, tf_mix(jA,         one) >> 31, 1u << o);
        insb(mB, tf_mix(jA + HALFN, one) >> 31, 1u << o);
    }

    for (int k = 0; k < 20; k++) {
        __syncthreads();   // protect previous iteration's sWh reads
        const float4* srcA = (const float4*)(Wh + (size_t)k        * 1200);
        const float4* srcB = (const float4*)(Wh + (size_t)(k + 20) * 1200);
        for (int i = tid; i < 300; i += TPB) {
            ((float4*)sWhA)[i] = srcA[i];
            ((float4*)sWhB)[i] = srcB[i];
        }
        __syncthreads();

        // masks for the NEXT k pair, built during this k's GEMM
        uint32_t nA = 0u, nB = 0u;
        const uint32_t nbase = (unsigned)(k + 1) * BT20 + base_b + 42u;

        #pragma unroll 1
        for (int oc = 0; oc < 5; oc++) {
            float y0v[4], y1v[4];
            #pragma unroll
            for (int u = 0; u < 4; u++) {
                const int o = oc * 4 + u;
                const float4* wA4 = (const float4*)(sWhA + o * 60);
                const float4* wB4 = (const float4*)(sWhB + o * 60);
                unsigned long long a0 = 0ull, a0b = 0ull, a1 = 0ull, a1b = 0ull;
                #pragma unroll
                for (int d = 0; d < 15; d++) {
                    float4 va = wA4[d];
                    float4 vb = wB4[d];
                    fma2(a0,  f2lo(va), h2[2*d]);
                    fma2(a0b, f2hi(va), h2[2*d+1]);
                    fma2(a1,  f2lo(vb), h2[2*d]);
                    fma2(a1b, f2hi(vb), h2[2*d+1]);
                }
                add2(a0, a0b);
                add2(a1, a1b);
                float pA, qA, pB, qB;
                unpack2(a0, pA, qA);
                unpack2(a1, pB, qB);
                float accA = (pA + qA) + sbh[k*20 + o];
                float accB = (pB + qB) + sbh[(k+20)*20 + o];
                y0v[u] = fmaxf(accA, 0.f) * keepf(mA, o);
                y1v[u] = fmaxf(accB, 0.f) * keepf(mB, o);

                // 2 threefry blocks for next-k masks (fills stall slots)
                uint32_t jn = nbase + (unsigned)o;
                insb(nA, tf_mix(jn,         one) >> 31, 1u << o);
                insb(nB, tf_mix(jn + HALFN, one) >> 31, 1u << o);
            }
            *(float4*)(out + (size_t)k        * BT20 + base_b + oc * 4) =
                make_float4(y0v[0], y0v[1], y0v[2], y0v[3]);
            *(float4*)(out + (size_t)(k + 20) * BT20 + base_b + oc * 4) =
                make_float4(y1v[0], y1v[1], y1v[2], y1v[3]);
        }
        mA = nA;
        mB = nB;
    }
}

extern "C" void kernel_launch(void* const* d_in, const int* in_sizes, int n_in,
                              void* d_out, int out_size) {
    const float* x  = (const float*)d_in[0];   // [131072, 20]
    const float* W1 = (const float*)d_in[1];   // [60, 20]
    const float* b1 = (const float*)d_in[2];   // [60]
    const float* Wh = (const float*)d_in[3];   // [40, 20, 60]
    const float* bh = (const float*)d_in[4];   // [40, 20]
    float* out = (float*)d_out;                // [40, 131072, 1, 20]

    const int rows = in_sizes[0] / 20;         // 131072
    fused_kernel<<<rows / TPB, TPB>>>(x, W1, b1, Wh, bh, out, 1u);
}